// round 16
// baseline (speedup 1.0000x reference)
#include <cuda_runtime.h>
#include <cuda_fp16.h>
#include <math.h>
#include <stdint.h>

#define BB 4
#define TT 8192
#define DDIM 512
#define HH 8
#define DH 64
#define MM (BB*TT)

#define QN_SCALE 65536.0f
#define QN_INV   (1.0f/65536.0f)

#define KC 64                    // halves per K chunk (128B rows)
#define NCH (DDIM/KC)            // 8
#define TILEB (128*128)          // 16 KB (128 rows x 128B)
// gemm1/gemmF: A 16K + B 16K per stage, 3 stages = 96 KB (2 CTAs/SM)
#define G1_A 0
#define G1_B TILEB
#define G1_STAGE (2*TILEB)
#define SM1 (3*G1_STAGE)
// ctx
#define CTX_TILES 8
#define CTX_CHUNKS 16

// Scratch
__device__ __half g_xq [(size_t)MM*DDIM];   // fp16 inputs
__device__ __half g_xk [(size_t)MM*DDIM];
__device__ __half g_xv [(size_t)MM*DDIM];
__device__ __half g_qhh[(size_t)MM*DDIM];
__device__ __half g_khh[(size_t)MM*DDIM];
__device__ __half g_vhh[(size_t)MM*DDIM];
__device__ __half g_qn [(size_t)MM*DDIM];
__device__ float g_ctx[BB*HH*DH*DH];
__device__ float g_ksum[BB*DDIM];           // [b][hc]
__device__ __half g_w1[3][DDIM*DDIM];       // Wq, Wk, Wv fp16
__device__ __half g_Ph[BB][DDIM*DDIM];      // P^T: [b][n][hc], fp16

// ---------------- helpers ----------------
__device__ __forceinline__ uint32_t smem_u32(const void* p) {
    uint32_t a;
    asm("{ .reg .u64 t; cvta.to.shared.u64 t, %1; cvt.u32.u64 %0, t; }" : "=r"(a) : "l"(p));
    return a;
}
__device__ __forceinline__ void ldsm4(uint32_t* r, uint32_t addr) {
    asm volatile("ldmatrix.sync.aligned.m8n8.x4.shared.b16 {%0,%1,%2,%3}, [%4];"
                 : "=r"(r[0]), "=r"(r[1]), "=r"(r[2]), "=r"(r[3]) : "r"(addr));
}
__device__ __forceinline__ void ldsm4t(uint32_t* r, uint32_t addr) {
    asm volatile("ldmatrix.sync.aligned.m8n8.x4.trans.shared.b16 {%0,%1,%2,%3}, [%4];"
                 : "=r"(r[0]), "=r"(r[1]), "=r"(r[2]), "=r"(r[3]) : "r"(addr));
}
__device__ __forceinline__ void mma_f16(float* c, const uint32_t* a, const uint32_t* b) {
    asm volatile("mma.sync.aligned.m16n8k16.row.col.f32.f16.f16.f32 "
                 "{%0,%1,%2,%3}, {%4,%5,%6,%7}, {%8,%9}, {%0,%1,%2,%3};"
                 : "+f"(c[0]), "+f"(c[1]), "+f"(c[2]), "+f"(c[3])
                 : "r"(a[0]), "r"(a[1]), "r"(a[2]), "r"(a[3]), "r"(b[0]), "r"(b[1]));
}
__device__ __forceinline__ void cpasync16(uint32_t dst, const void* src) {
    asm volatile("cp.async.cg.shared.global [%0], [%1], 16;" :: "r"(dst), "l"(src) : "memory");
}
__device__ __forceinline__ void cp_commit() { asm volatile("cp.async.commit_group;" ::: "memory"); }
__device__ __forceinline__ void cp_wait0()  { asm volatile("cp.async.wait_group 0;" ::: "memory"); }
__device__ __forceinline__ void cp_wait1()  { asm volatile("cp.async.wait_group 1;" ::: "memory"); }
__device__ __forceinline__ uint32_t swz(int r, int u) {   // 128B rows, 16B units
    return (uint32_t)(r * 128 + ((u ^ (r & 7)) << 4));
}
__device__ __forceinline__ uint32_t sbase(int r) {        // swz(r,u) == sbase(r) ^ (u<<4)
    return (uint32_t)(r * 128 + ((r & 7) << 4));
}

// ---------------- pre-conversion ----------------
__global__ void precvt_w1(const float* __restrict__ Wq, const float* __restrict__ Wk,
                          const float* __restrict__ Wv) {
    const int idx = blockIdx.x * blockDim.x + threadIdx.x;
    const int w = blockIdx.y;
    const float* src = (w == 0) ? Wq : (w == 1) ? Wk : Wv;
    float4 v = *(const float4*)(src + (size_t)idx * 4);
    __half2 h01 = __floats2half2_rn(v.x, v.y);
    __half2 h23 = __floats2half2_rn(v.z, v.w);
    uint2 h = { *reinterpret_cast<uint32_t*>(&h01), *reinterpret_cast<uint32_t*>(&h23) };
    *(uint2*)((char*)g_w1[w] + (size_t)idx * 8) = h;
}
__global__ void precvt_x(const float* __restrict__ q, const float* __restrict__ k,
                         const float* __restrict__ v) {
    const size_t idx = (size_t)blockIdx.x * blockDim.x + threadIdx.x;
    const int w = blockIdx.y;
    const float* src = (w == 0) ? q : (w == 1) ? k : v;
    __half* dst = (w == 0) ? g_xq : (w == 1) ? g_xk : g_xv;
    float4 val = *(const float4*)(src + idx * 4);
    __half2 h01 = __floats2half2_rn(val.x, val.y);
    __half2 h23 = __floats2half2_rn(val.z, val.w);
    uint2 h = { *reinterpret_cast<uint32_t*>(&h01), *reinterpret_cast<uint32_t*>(&h23) };
    *(uint2*)((char*)dst + idx * 8) = h;
}

// ---------------- 1-term GEMM (q/k/v): pure cp.async, hoisted addressing ----------------
__global__ void __launch_bounds__(256, 2)
gemm1(const float* __restrict__ bq, const float* __restrict__ bk,
      const float* __restrict__ bv)
{
    extern __shared__ char smem[];
    const int z = blockIdx.z;
    const __half* Xh = (z == 0) ? g_xq : (z == 1) ? g_xk : g_xv;
    const float* bias = (z == 0) ? bq : (z == 1) ? bk : bv;
    const __half* W = g_w1[z];
    __half* Y = (z == 0) ? g_qhh : (z == 1) ? g_khh : g_vhh;
    const int act = (z < 2);

    const uint32_t sb = smem_u32(smem);
    const int tid = threadIdx.x;
    const int wid = tid >> 5, lane = tid & 31;
    const int wm = wid >> 2, wn = wid & 3;       // 2 m-warps x 4 n-warps
    const int g = lane >> 2, tg = lane & 3;
    const int m0 = blockIdx.y * 128, n0 = blockIdx.x * 128;

    float acc[4][4][4];
#pragma unroll
    for (int i = 0; i < 4; i++)
#pragma unroll
        for (int j = 0; j < 4; j++)
#pragma unroll
            for (int r = 0; r < 4; r++) acc[i][j][r] = 0.f;

    const int r0 = tid >> 3, u0 = tid & 7;
    const uint32_t dA = sb + G1_A + swz(r0, u0);
    const uint32_t dB = sb + G1_B + swz(r0, u0);
    const char* pA = (const char*)Xh + ((size_t)(m0 + r0) * DDIM) * 2 + u0 * 16;
    const char* pB = (const char*)W  + ((size_t)(n0 + r0) * DDIM) * 2 + u0 * 16;

    auto issue = [&](int stage, int kc) {
        const uint32_t so = (uint32_t)(stage * G1_STAGE);
        const int ko = kc * 128;
#pragma unroll
        for (int it = 0; it < 4; it++) {
            cpasync16(dA + so + it * 4096, pA + it * 32768 + ko);
            cpasync16(dB + so + it * 4096, pB + it * 32768 + ko);
        }
        cp_commit();
    };

    uint32_t aB[4], bB[2];
#pragma unroll
    for (int mi = 0; mi < 4; mi++)
        aB[mi] = (uint32_t)G1_A + sbase(wm * 64 + mi * 16 + (lane & 15));
#pragma unroll
    for (int np = 0; np < 2; np++)
        bB[np] = (uint32_t)G1_B + sbase(wn * 32 + np * 16 + ((lane >> 4) << 3) + (lane & 7));
    const uint32_t aX = (uint32_t)(lane >> 4) << 4;
    const uint32_t bX = (uint32_t)((lane >> 3) & 1) << 4;

    issue(0, 0);
    issue(1, 1);

    for (int kc = 0; kc < NCH; kc++) {
        if (kc < NCH - 1) cp_wait1(); else cp_wait0();
        __syncthreads();
        if (kc + 2 < NCH) issue((kc + 2) % 3, kc + 2);

        const uint32_t st = sb + (kc % 3) * G1_STAGE;
#pragma unroll
        for (int ks = 0; ks < 4; ks++) {
            const uint32_t kx = (uint32_t)(ks * 2) << 4;
            uint32_t ah[4][4];
#pragma unroll
            for (int mi = 0; mi < 4; mi++)
                ldsm4(ah[mi], st + (aB[mi] ^ (kx | aX)));
#pragma unroll
            for (int np = 0; np < 2; np++) {
                uint32_t r4[4];
                ldsm4(r4, st + (bB[np] ^ (kx | bX)));
                uint32_t b0[2] = {r4[0], r4[1]}, b1[2] = {r4[2], r4[3]};
#pragma unroll
                for (int mi = 0; mi < 4; mi++) {
                    mma_f16(acc[mi][np*2+0], ah[mi], b0);
                    mma_f16(acc[mi][np*2+1], ah[mi], b1);
                }
            }
        }
        __syncthreads();
    }

#pragma unroll
    for (int mi = 0; mi < 4; mi++)
#pragma unroll
        for (int ni = 0; ni < 4; ni++) {
            const int col = n0 + wn * 32 + ni * 8 + tg * 2;
            const float b0 = bias[col], b1 = bias[col + 1];
#pragma unroll
            for (int half = 0; half < 2; half++) {
                const int row = m0 + wm * 64 + mi * 16 + g + half * 8;
                float x = acc[mi][ni][half * 2 + 0] + b0;
                float y = acc[mi][ni][half * 2 + 1] + b1;
                if (act) {
                    x = (x > 0.f) ? x + 1.f : expf(x);
                    y = (y > 0.f) ? y + 1.f : expf(y);
                }
                __half2 h = __floats2half2_rn(x, y);
                *(uint32_t*)((char*)Y + ((size_t)row * DDIM + col) * 2) =
                    *reinterpret_cast<uint32_t*>(&h);
            }
        }
}

// ---------------- zero ----------------
__global__ void zero_kernel()
{
    int i = blockIdx.x * blockDim.x + threadIdx.x;
    if (i < BB*HH*DH*DH) g_ctx[i]  = 0.f;
    if (i < BB*DDIM)     g_ksum[i] = 0.f;
}

// ---------------- ctx via tensor cores, hoisted addressing ----------------
__global__ __launch_bounds__(256)
void ctx_kernel()
{
    __shared__ __align__(128) char smem[2 * 16384];
    const int bh = blockIdx.x, chunk = blockIdx.y;
    const int b = bh >> 3, h = bh & 7;
    const uint32_t sb = smem_u32(smem);
    const int tid = threadIdx.x, wid = tid >> 5, lane = tid & 31;
    const int wc = wid >> 1, wd = wid & 1;

    float acc[4][4];
#pragma unroll
    for (int i = 0; i < 4; i++)
#pragma unroll
        for (int j = 0; j < 4; j++) acc[i][j] = 0.f;
    float ksacc = 0.f;

    const int t0g = b * TT + chunk * (TT / CTX_CHUNKS);

    const int r0 = tid >> 3, u0 = tid & 7;
    const uint32_t dK = sb + swz(r0, u0);
    const char* pK = (const char*)g_khh + ((size_t)(t0g + r0) * DDIM + h * DH) * 2 + u0 * 16;
    const char* pV = (const char*)g_vhh + ((size_t)(t0g + r0) * DDIM + h * DH) * 2 + u0 * 16;

    auto issue = [&](int stage, int tile) {
        const uint32_t so = (uint32_t)(stage * 16384);
        const int to = tile * 65536;   // 64 rows * 1024 B
#pragma unroll
        for (int it = 0; it < 2; it++) {
            cpasync16(dK + so + it * 4096, pK + to + it * 32768);
            cpasync16(dK + 8192 + so + it * 4096, pV + to + it * 32768);
        }
        cp_commit();
    };

    const int trow_l = (lane & 7) + ((lane >> 4) << 3);
    const int usel = (lane >> 3) & 1;

    issue(0, 0);
    for (int tile = 0; tile < CTX_TILES; tile++) {
        cp_wait0();
        __syncthreads();
        if (tile + 1 < CTX_TILES) issue((tile + 1) & 1, tile + 1);

        const uint32_t st = sb + (tile & 1) * 16384;

        if (tid < 64) {
            const int u = tid >> 3, byo = (tid & 7) * 2;
#pragma unroll 16
            for (int t = 0; t < 64; t++) {
                unsigned short hv;
                uint32_t a = st + swz(t, u) + byo;
                asm volatile("ld.shared.u16 %0, [%1];" : "=h"(hv) : "r"(a));
                ksacc += __half2float(*reinterpret_cast<__half*>(&hv));
            }
        }

#pragma unroll
        for (int ks = 0; ks < 4; ks++) {
            const int trow = ks * 16 + trow_l;
            uint32_t a4[4];
            ldsm4t(a4, st + swz(trow, wc * 2 + usel));
            uint32_t b4a[4], b4b[4];
            ldsm4t(b4a, st + 8192 + swz(trow, wd * 4 + usel));
            ldsm4t(b4b, st + 8192 + swz(trow, wd * 4 + 2 + usel));
            uint32_t bb[4][2] = {{b4a[0], b4a[2]}, {b4a[1], b4a[3]},
                                 {b4b[0], b4b[2]}, {b4b[1], b4b[3]}};
#pragma unroll
            for (int db = 0; db < 4; db++)
                mma_f16(acc[db], a4, bb[db]);
        }
        __syncthreads();
    }

    float* cp = g_ctx + bh * 4096;
    const int g = lane >> 2, tg2 = lane & 3;
#pragma unroll
    for (int db = 0; db < 4; db++)
#pragma unroll
        for (int half = 0; half < 2; half++) {
            const int c = wc * 16 + g + half * 8;
            const int d = wd * 32 + db * 8 + tg2 * 2;
            atomicAdd(&cp[c * 64 + d + 0], acc[db][half * 2 + 0]);
            atomicAdd(&cp[c * 64 + d + 1], acc[db][half * 2 + 1]);
        }
    if (tid < 64) atomicAdd(&g_ksum[b * DDIM + h * DH + tid], ksacc);
}

// ---------------- P: PT[b][n][hc] = sum_d ctx_bh[c][d] * Wo[n][h*64+d] (fp16) ----------------
__global__ __launch_bounds__(256)
void p_kernel(const float* __restrict__ Wo)
{
    const int n = blockIdx.x, b = blockIdx.y;
    const int tid = threadIdx.x;
    __shared__ float wo[DDIM];
    wo[tid] = Wo[(size_t)n * DDIM + tid];
    wo[tid + 256] = Wo[(size_t)n * DDIM + 256 + tid];
    __syncthreads();

#pragma unroll
    for (int q = 0; q < 2; q++) {
        const int hc = q * 256 + tid;
        const int h = hc >> 6, c = hc & 63;
        const float* cr = g_ctx + ((size_t)(b * 8 + h) * 64 + c) * 64;
        float s = 0.f;
#pragma unroll
        for (int d = 0; d < 64; d++) s += cr[d] * wo[h * 64 + d];
        g_Ph[b][(size_t)n * DDIM + hc] = __float2half_rn(s);
    }
}

// ---------------- qn: den[t,h] = qh.ksum; qn = qh * (QN_SCALE/den) ----------------
__global__ __launch_bounds__(256)
void qn_kernel()
{
    const int b = blockIdx.y;
    const int t0 = blockIdx.x * 64;
    const int tid = threadIdx.x;
    __shared__ float ks[DDIM];
    if (tid < 128) *(float4*)&ks[tid * 4] = *(const float4*)(g_ksum + b * DDIM + tid * 4);
    __syncthreads();

    const int t = tid >> 2, sub = tid & 3;
    const size_t rowofs = ((size_t)(b * TT + t0 + t) * DDIM + sub * 128) * 2;
    const uint4* qrow = (const uint4*)((const char*)g_qhh + rowofs);

    uint4 qv[16];
#pragma unroll
    for (int i = 0; i < 16; i++) qv[i] = qrow[i];

    float d0 = 0.f, d1 = 0.f;
#pragma unroll
    for (int i = 0; i < 16; i++) {
        const uint32_t w[4] = {qv[i].x, qv[i].y, qv[i].z, qv[i].w};
        float acc = 0.f;
#pragma unroll
        for (int j = 0; j < 4; j++) {
            float2 f = __half22float2(*reinterpret_cast<const __half2*>(&w[j]));
            const int hc = sub * 128 + i * 8 + j * 2;
            acc += f.x * ks[hc] + f.y * ks[hc + 1];
        }
        if (i < 8) d0 += acc; else d1 += acc;
    }
    const float inv0 = QN_SCALE / d0, inv1 = QN_SCALE / d1;

    uint4* qd = (uint4*)((char*)g_qn + rowofs);
#pragma unroll
    for (int i = 0; i < 16; i++) {
        const float inv = (i < 8) ? inv0 : inv1;
        uint32_t w[4] = {qv[i].x, qv[i].y, qv[i].z, qv[i].w};
#pragma unroll
        for (int j = 0; j < 4; j++) {
            float2 f = __half22float2(*reinterpret_cast<const __half2*>(&w[j]));
            __half2 o = __floats2half2_rn(f.x * inv, f.y * inv);
            w[j] = *reinterpret_cast<uint32_t*>(&o);
        }
        qd[i] = make_uint4(w[0], w[1], w[2], w[3]);
    }
}

// ---------------- final GEMM: 1-term (qn @ Ph^T)*QN_INV + bo, 3-stage ----------------
__global__ void __launch_bounds__(256, 2)
gemmF(const float* __restrict__ bo, float* __restrict__ Y)
{
    extern __shared__ char smem[];
    const uint32_t sb = smem_u32(smem);
    const int tid = threadIdx.x;
    const int wid = tid >> 5, lane = tid & 31;
    const int wm = wid >> 2, wn = wid & 3;
    const int g = lane >> 2, tg = lane & 3;
    const int m0 = blockIdx.y * 128, n0 = blockIdx.x * 128;
    const int b = blockIdx.y >> 6;
    const __half* Ph = g_Ph[b];

    float acc[4][4][4];
#pragma unroll
    for (int i = 0; i < 4; i++)
#pragma unroll
        for (int j = 0; j < 4; j++)
#pragma unroll
            for (int r = 0; r < 4; r++) acc[i][j][r] = 0.f;

    const int r0 = tid >> 3, u0 = tid & 7;
    const uint32_t dA = sb + G1_A + swz(r0, u0);
    const uint32_t dB = sb + G1_B + swz(r0, u0);
    const char* pA = (const char*)g_qn + ((size_t)(m0 + r0) * DDIM) * 2 + u0 * 16;
    const char* pB = (const char*)Ph   + ((size_t)(n0 + r0) * DDIM) * 2 + u0 * 16;

    auto issue = [&](int stage, int kc) {
        const uint32_t so = (uint32_t)(stage * G1_STAGE);
        const int ko = kc * 128;
#pragma unroll
        for (int it = 0; it < 4; it++) {
            cpasync16(dA + so + it * 4096, pA + it * 32768 + ko);
            cpasync16(dB + so + it * 4096, pB + it * 32768 + ko);
        }
        cp_commit();
    };

    uint32_t aB[4], bB[2];
#pragma unroll
    for (int mi = 0; mi < 4; mi++)
        aB[mi] = (uint32_t)G1_A + sbase(wm * 64 + mi * 16 + (lane & 15));
#pragma unroll
    for (int np = 0; np < 2; np++)
        bB[np] = (uint32_t)G1_B + sbase(wn * 32 + np * 16 + ((lane >> 4) << 3) + (lane & 7));
    const uint32_t aX = (uint32_t)(lane >> 4) << 4;
    const uint32_t bX = (uint32_t)((lane >> 3) & 1) << 4;

    issue(0, 0);
    issue(1, 1);

    for (int kc = 0; kc < NCH; kc++) {
        if (kc < NCH - 1) cp_wait1(); else cp_wait0();
        __syncthreads();
        if (kc + 2 < NCH) issue((kc + 2) % 3, kc + 2);

        const uint32_t st = sb + (kc % 3) * G1_STAGE;
#pragma unroll
        for (int ks = 0; ks < 4; ks++) {
            const uint32_t kx = (uint32_t)(ks * 2) << 4;
            uint32_t ah[4][4];
#pragma unroll
            for (int mi = 0; mi < 4; mi++)
                ldsm4(ah[mi], st + (aB[mi] ^ (kx | aX)));
#pragma unroll
            for (int np = 0; np < 2; np++) {
                uint32_t r4[4];
                ldsm4(r4, st + (bB[np] ^ (kx | bX)));
                uint32_t b0[2] = {r4[0], r4[1]}, b1[2] = {r4[2], r4[3]};
#pragma unroll
                for (int mi = 0; mi < 4; mi++) {
                    mma_f16(acc[mi][np*2+0], ah[mi], b0);
                    mma_f16(acc[mi][np*2+1], ah[mi], b1);
                }
            }
        }
        __syncthreads();
    }

#pragma unroll
    for (int mi = 0; mi < 4; mi++)
#pragma unroll
        for (int ni = 0; ni < 4; ni++) {
            const int col = n0 + wn * 32 + ni * 8 + tg * 2;
            const float b0 = bo[col], b1 = bo[col + 1];
#pragma unroll
            for (int half = 0; half < 2; half++) {
                const int row = m0 + wm * 64 + mi * 16 + g + half * 8;
                float2 o;
                o.x = acc[mi][ni][half * 2 + 0] * QN_INV + b0;
                o.y = acc[mi][ni][half * 2 + 1] * QN_INV + b1;
                *(float2*)(Y + (size_t)row * DDIM + col) = o;
            }
        }
}

// ---------------- launch ----------------
extern "C" void kernel_launch(void* const* d_in, const int* in_sizes, int n_in,
                              void* d_out, int out_size)
{
    const float* q  = (const float*)d_in[0];
    const float* k  = (const float*)d_in[1];
    const float* v  = (const float*)d_in[2];
    const float* Wq = (const float*)d_in[3];
    const float* bq = (const float*)d_in[4];
    const float* Wk = (const float*)d_in[5];
    const float* bk = (const float*)d_in[6];
    const float* Wv = (const float*)d_in[7];
    const float* bv = (const float*)d_in[8];
    const float* Wo = (const float*)d_in[9];
    const float* bo = (const float*)d_in[10];
    float* out = (float*)d_out;

    cudaFuncSetAttribute((const void*)gemm1, cudaFuncAttributeMaxDynamicSharedMemorySize, SM1);
    cudaFuncSetAttribute((const void*)gemmF, cudaFuncAttributeMaxDynamicSharedMemorySize, SM1);

    precvt_w1<<<dim3(256, 3), 256>>>(Wq, Wk, Wv);
    precvt_x<<<dim3(MM*DDIM/4/256, 3), 256>>>(q, k, v);
    zero_kernel<<<(BB*HH*DH*DH + 255)/256, 256>>>();
    gemm1<<<dim3(4, 256, 3), 256, SM1>>>(bq, bk, bv);            // qh/kh/vh fp16
    ctx_kernel<<<dim3(BB*HH, CTX_CHUNKS), 256>>>();              // ctx, ksum (HMMA)
    p_kernel<<<dim3(DDIM, BB), 256>>>(Wo);                       // PT fp16
    qn_kernel<<<dim3(TT/64, BB), 256>>>();                       // qn = qh*(S/den)
    gemmF<<<dim3(4, 256), 256, SM1>>>(bo, out);                  // out = qn@PT^T*1/S + bo
}

// round 17
// speedup vs baseline: 1.5461x; 1.5461x over previous
#include <cuda_runtime.h>
#include <cuda_fp16.h>
#include <math.h>
#include <stdint.h>

#define BB 4
#define TT 8192
#define DDIM 512
#define HH 8
#define DH 64
#define MM (BB*TT)

#define QN_SCALE 65536.0f
#define QN_INV   (1.0f/65536.0f)

#define KC 64                    // halves per K chunk (128B rows)
#define NCH (DDIM/KC)            // 8
#define TILEB (128*128)          // 16 KB (128 rows x 128B)
// gemm1/gemmF: A 16K + B 16K per stage, 3 stages = 96 KB (2 CTAs/SM)
#define G1_A 0
#define G1_B TILEB
#define G1_STAGE (2*TILEB)
#define SM1 (3*G1_STAGE)
// ctx
#define CTX_TILES 8
#define CTX_CHUNKS 16

// Scratch
__device__ __half g_xq [(size_t)MM*DDIM];   // fp16 inputs
__device__ __half g_xk [(size_t)MM*DDIM];
__device__ __half g_xv [(size_t)MM*DDIM];
__device__ __half g_qhh[(size_t)MM*DDIM];
__device__ __half g_khh[(size_t)MM*DDIM];
__device__ __half g_vhh[(size_t)MM*DDIM];
__device__ __half g_qn [(size_t)MM*DDIM];
__device__ float g_ctx[BB*HH*DH*DH];
__device__ float g_ksum[BB*DDIM];           // [b][hc]
__device__ __half g_w1[3][DDIM*DDIM];       // Wq, Wk, Wv fp16
__device__ __half g_Ph[BB][DDIM*DDIM];      // P^T: [b][n][hc], fp16

// ---------------- helpers ----------------
__device__ __forceinline__ uint32_t smem_u32(const void* p) {
    uint32_t a;
    asm("{ .reg .u64 t; cvta.to.shared.u64 t, %1; cvt.u32.u64 %0, t; }" : "=r"(a) : "l"(p));
    return a;
}
__device__ __forceinline__ void ldsm4(uint32_t* r, uint32_t addr) {
    asm volatile("ldmatrix.sync.aligned.m8n8.x4.shared.b16 {%0,%1,%2,%3}, [%4];"
                 : "=r"(r[0]), "=r"(r[1]), "=r"(r[2]), "=r"(r[3]) : "r"(addr));
}
__device__ __forceinline__ void ldsm4t(uint32_t* r, uint32_t addr) {
    asm volatile("ldmatrix.sync.aligned.m8n8.x4.trans.shared.b16 {%0,%1,%2,%3}, [%4];"
                 : "=r"(r[0]), "=r"(r[1]), "=r"(r[2]), "=r"(r[3]) : "r"(addr));
}
__device__ __forceinline__ void mma_f16(float* c, const uint32_t* a, const uint32_t* b) {
    asm volatile("mma.sync.aligned.m16n8k16.row.col.f32.f16.f16.f32 "
                 "{%0,%1,%2,%3}, {%4,%5,%6,%7}, {%8,%9}, {%0,%1,%2,%3};"
                 : "+f"(c[0]), "+f"(c[1]), "+f"(c[2]), "+f"(c[3])
                 : "r"(a[0]), "r"(a[1]), "r"(a[2]), "r"(a[3]), "r"(b[0]), "r"(b[1]));
}
__device__ __forceinline__ void cpasync16(uint32_t dst, const void* src) {
    asm volatile("cp.async.cg.shared.global [%0], [%1], 16;" :: "r"(dst), "l"(src) : "memory");
}
__device__ __forceinline__ void cp_commit() { asm volatile("cp.async.commit_group;" ::: "memory"); }
__device__ __forceinline__ void cp_wait0()  { asm volatile("cp.async.wait_group 0;" ::: "memory"); }
__device__ __forceinline__ void cp_wait1()  { asm volatile("cp.async.wait_group 1;" ::: "memory"); }
__device__ __forceinline__ uint32_t swz(int r, int u) {   // 128B rows, 16B units
    return (uint32_t)(r * 128 + ((u ^ (r & 7)) << 4));
}
__device__ __forceinline__ uint32_t sbase(int r) {        // swz(r,u) == sbase(r) ^ (u<<4)
    return (uint32_t)(r * 128 + ((r & 7) << 4));
}

// ---------------- pre-conversion ----------------
__global__ void precvt_w1(const float* __restrict__ Wq, const float* __restrict__ Wk,
                          const float* __restrict__ Wv) {
    const int idx = blockIdx.x * blockDim.x + threadIdx.x;
    const int w = blockIdx.y;
    const float* src = (w == 0) ? Wq : (w == 1) ? Wk : Wv;
    float4 v = *(const float4*)(src + (size_t)idx * 4);
    __half2 h01 = __floats2half2_rn(v.x, v.y);
    __half2 h23 = __floats2half2_rn(v.z, v.w);
    uint2 h = { *reinterpret_cast<uint32_t*>(&h01), *reinterpret_cast<uint32_t*>(&h23) };
    *(uint2*)((char*)g_w1[w] + (size_t)idx * 8) = h;
}
__global__ void precvt_x(const float* __restrict__ q, const float* __restrict__ k,
                         const float* __restrict__ v) {
    const size_t idx = (size_t)blockIdx.x * blockDim.x + threadIdx.x;
    const int w = blockIdx.y;
    const float* src = (w == 0) ? q : (w == 1) ? k : v;
    __half* dst = (w == 0) ? g_xq : (w == 1) ? g_xk : g_xv;
    float4 val = *(const float4*)(src + idx * 4);
    __half2 h01 = __floats2half2_rn(val.x, val.y);
    __half2 h23 = __floats2half2_rn(val.z, val.w);
    uint2 h = { *reinterpret_cast<uint32_t*>(&h01), *reinterpret_cast<uint32_t*>(&h23) };
    *(uint2*)((char*)dst + idx * 8) = h;
}

// ---------------- 1-term GEMM (q/k/v): pure cp.async, hoisted addressing ----------------
__global__ void __launch_bounds__(256, 2)
gemm1(const float* __restrict__ bq, const float* __restrict__ bk,
      const float* __restrict__ bv)
{
    extern __shared__ char smem[];
    const int z = blockIdx.z;
    const __half* Xh = (z == 0) ? g_xq : (z == 1) ? g_xk : g_xv;
    const float* bias = (z == 0) ? bq : (z == 1) ? bk : bv;
    const __half* W = g_w1[z];
    __half* Y = (z == 0) ? g_qhh : (z == 1) ? g_khh : g_vhh;
    const int act = (z < 2);

    const uint32_t sb = smem_u32(smem);
    const int tid = threadIdx.x;
    const int wid = tid >> 5, lane = tid & 31;
    const int wm = wid >> 2, wn = wid & 3;       // 2 m-warps x 4 n-warps
    const int g = lane >> 2, tg = lane & 3;
    const int m0 = blockIdx.y * 128, n0 = blockIdx.x * 128;

    float acc[4][4][4];
#pragma unroll
    for (int i = 0; i < 4; i++)
#pragma unroll
        for (int j = 0; j < 4; j++)
#pragma unroll
            for (int r = 0; r < 4; r++) acc[i][j][r] = 0.f;

    const int r0 = tid >> 3, u0 = tid & 7;
    const uint32_t dA = sb + G1_A + swz(r0, u0);
    const uint32_t dB = sb + G1_B + swz(r0, u0);
    const char* pA = (const char*)Xh + ((size_t)(m0 + r0) * DDIM) * 2 + u0 * 16;
    const char* pB = (const char*)W  + ((size_t)(n0 + r0) * DDIM) * 2 + u0 * 16;

    auto issue = [&](int stage, int kc) {
        const uint32_t so = (uint32_t)(stage * G1_STAGE);
        const int ko = kc * 128;
#pragma unroll
        for (int it = 0; it < 4; it++) {
            cpasync16(dA + so + it * 4096, pA + it * 32768 + ko);
            cpasync16(dB + so + it * 4096, pB + it * 32768 + ko);
        }
        cp_commit();
    };

    uint32_t aB[4], bB[2];
#pragma unroll
    for (int mi = 0; mi < 4; mi++)
        aB[mi] = (uint32_t)G1_A + sbase(wm * 64 + mi * 16 + (lane & 15));
#pragma unroll
    for (int np = 0; np < 2; np++)
        bB[np] = (uint32_t)G1_B + sbase(wn * 32 + np * 16 + ((lane >> 4) << 3) + (lane & 7));
    const uint32_t aX = (uint32_t)(lane >> 4) << 4;
    const uint32_t bX = (uint32_t)((lane >> 3) & 1) << 4;

    issue(0, 0);
    issue(1, 1);

    for (int kc = 0; kc < NCH; kc++) {
        if (kc < NCH - 1) cp_wait1(); else cp_wait0();
        __syncthreads();
        if (kc + 2 < NCH) issue((kc + 2) % 3, kc + 2);

        const uint32_t st = sb + (kc % 3) * G1_STAGE;
#pragma unroll
        for (int ks = 0; ks < 4; ks++) {
            const uint32_t kx = (uint32_t)(ks * 2) << 4;
            uint32_t ah[4][4];
#pragma unroll
            for (int mi = 0; mi < 4; mi++)
                ldsm4(ah[mi], st + (aB[mi] ^ (kx | aX)));
#pragma unroll
            for (int np = 0; np < 2; np++) {
                uint32_t r4[4];
                ldsm4(r4, st + (bB[np] ^ (kx | bX)));
                uint32_t b0[2] = {r4[0], r4[1]}, b1[2] = {r4[2], r4[3]};
#pragma unroll
                for (int mi = 0; mi < 4; mi++) {
                    mma_f16(acc[mi][np*2+0], ah[mi], b0);
                    mma_f16(acc[mi][np*2+1], ah[mi], b1);
                }
            }
        }
        __syncthreads();
    }

#pragma unroll
    for (int mi = 0; mi < 4; mi++)
#pragma unroll
        for (int ni = 0; ni < 4; ni++) {
            const int col = n0 + wn * 32 + ni * 8 + tg * 2;
            const float b0 = bias[col], b1 = bias[col + 1];
#pragma unroll
            for (int half = 0; half < 2; half++) {
                const int row = m0 + wm * 64 + mi * 16 + g + half * 8;
                float x = acc[mi][ni][half * 2 + 0] + b0;
                float y = acc[mi][ni][half * 2 + 1] + b1;
                if (act) {
                    x = (x > 0.f) ? x + 1.f : expf(x);
                    y = (y > 0.f) ? y + 1.f : expf(y);
                }
                __half2 h = __floats2half2_rn(x, y);
                *(uint32_t*)((char*)Y + ((size_t)row * DDIM + col) * 2) =
                    *reinterpret_cast<uint32_t*>(&h);
            }
        }
}

// ---------------- zero ----------------
__global__ void zero_kernel()
{
    int i = blockIdx.x * blockDim.x + threadIdx.x;
    if (i < BB*HH*DH*DH) g_ctx[i]  = 0.f;
    if (i < BB*DDIM)     g_ksum[i] = 0.f;
}

// ---------------- ctx via tensor cores, hoisted addressing ----------------
__global__ __launch_bounds__(256)
void ctx_kernel()
{
    __shared__ __align__(128) char smem[2 * 16384];
    const int bh = blockIdx.x, chunk = blockIdx.y;
    const int b = bh >> 3, h = bh & 7;
    const uint32_t sb = smem_u32(smem);
    const int tid = threadIdx.x, wid = tid >> 5, lane = tid & 31;
    const int wc = wid >> 1, wd = wid & 1;

    float acc[4][4];
#pragma unroll
    for (int i = 0; i < 4; i++)
#pragma unroll
        for (int j = 0; j < 4; j++) acc[i][j] = 0.f;
    float ksacc = 0.f;

    const int t0g = b * TT + chunk * (TT / CTX_CHUNKS);

    const int r0 = tid >> 3, u0 = tid & 7;
    const uint32_t dK = sb + swz(r0, u0);
    const char* pK = (const char*)g_khh + ((size_t)(t0g + r0) * DDIM + h * DH) * 2 + u0 * 16;
    const char* pV = (const char*)g_vhh + ((size_t)(t0g + r0) * DDIM + h * DH) * 2 + u0 * 16;

    auto issue = [&](int stage, int tile) {
        const uint32_t so = (uint32_t)(stage * 16384);
        const int to = tile * 65536;   // 64 rows * 1024 B
#pragma unroll
        for (int it = 0; it < 2; it++) {
            cpasync16(dK + so + it * 4096, pK + to + it * 32768);
            cpasync16(dK + 8192 + so + it * 4096, pV + to + it * 32768);
        }
        cp_commit();
    };

    const int trow_l = (lane & 7) + ((lane >> 4) << 3);
    const int usel = (lane >> 3) & 1;

    issue(0, 0);
    for (int tile = 0; tile < CTX_TILES; tile++) {
        cp_wait0();
        __syncthreads();
        if (tile + 1 < CTX_TILES) issue((tile + 1) & 1, tile + 1);

        const uint32_t st = sb + (tile & 1) * 16384;

        if (tid < 64) {
            const int u = tid >> 3, byo = (tid & 7) * 2;
#pragma unroll 16
            for (int t = 0; t < 64; t++) {
                unsigned short hv;
                uint32_t a = st + swz(t, u) + byo;
                asm volatile("ld.shared.u16 %0, [%1];" : "=h"(hv) : "r"(a));
                ksacc += __half2float(*reinterpret_cast<__half*>(&hv));
            }
        }

#pragma unroll
        for (int ks = 0; ks < 4; ks++) {
            const int trow = ks * 16 + trow_l;
            uint32_t a4[4];
            ldsm4t(a4, st + swz(trow, wc * 2 + usel));
            uint32_t b4a[4], b4b[4];
            ldsm4t(b4a, st + 8192 + swz(trow, wd * 4 + usel));
            ldsm4t(b4b, st + 8192 + swz(trow, wd * 4 + 2 + usel));
            uint32_t bb[4][2] = {{b4a[0], b4a[2]}, {b4a[1], b4a[3]},
                                 {b4b[0], b4b[2]}, {b4b[1], b4b[3]}};
#pragma unroll
            for (int db = 0; db < 4; db++)
                mma_f16(acc[db], a4, bb[db]);
        }
        __syncthreads();
    }

    float* cp = g_ctx + bh * 4096;
    const int g = lane >> 2, tg2 = lane & 3;
#pragma unroll
    for (int db = 0; db < 4; db++)
#pragma unroll
        for (int half = 0; half < 2; half++) {
            const int c = wc * 16 + g + half * 8;
            const int d = wd * 32 + db * 8 + tg2 * 2;
            atomicAdd(&cp[c * 64 + d + 0], acc[db][half * 2 + 0]);
            atomicAdd(&cp[c * 64 + d + 1], acc[db][half * 2 + 1]);
        }
    if (tid < 64) atomicAdd(&g_ksum[b * DDIM + h * DH + tid], ksacc);
}

// ---------------- P: PT[b][n][hc] = sum_d ctx_bh[c][d] * Wo[n][h*64+d] (fp16) ----------------
__global__ __launch_bounds__(256)
void p_kernel(const float* __restrict__ Wo)
{
    const int n = blockIdx.x, b = blockIdx.y;
    const int tid = threadIdx.x;
    __shared__ float wo[DDIM];
    wo[tid] = Wo[(size_t)n * DDIM + tid];
    wo[tid + 256] = Wo[(size_t)n * DDIM + 256 + tid];
    __syncthreads();

#pragma unroll
    for (int q = 0; q < 2; q++) {
        const int hc = q * 256 + tid;
        const int h = hc >> 6, c = hc & 63;
        const float* cr = g_ctx + ((size_t)(b * 8 + h) * 64 + c) * 64;
        float s = 0.f;
#pragma unroll
        for (int d = 0; d < 64; d++) s += cr[d] * wo[h * 64 + d];
        g_Ph[b][(size_t)n * DDIM + hc] = __float2half_rn(s);
    }
}

// ---------------- qn: den[t,h] = qh.ksum; qn = qh * (QN_SCALE/den) ----------------
__global__ __launch_bounds__(256)
void qn_kernel()
{
    const int b = blockIdx.y;
    const int t0 = blockIdx.x * 64;
    const int tid = threadIdx.x;
    __shared__ float ks[DDIM];
    if (tid < 128) *(float4*)&ks[tid * 4] = *(const float4*)(g_ksum + b * DDIM + tid * 4);
    __syncthreads();

    const int t = tid >> 2, sub = tid & 3;
    const size_t rowofs = ((size_t)(b * TT + t0 + t) * DDIM + sub * 128) * 2;
    const uint4* qrow = (const uint4*)((const char*)g_qhh + rowofs);

    uint4 qv[16];
#pragma unroll
    for (int i = 0; i < 16; i++) qv[i] = qrow[i];

    float d0 = 0.f, d1 = 0.f;
#pragma unroll
    for (int i = 0; i < 16; i++) {
        const uint32_t w[4] = {qv[i].x, qv[i].y, qv[i].z, qv[i].w};
        float acc = 0.f;
#pragma unroll
        for (int j = 0; j < 4; j++) {
            float2 f = __half22float2(*reinterpret_cast<const __half2*>(&w[j]));
            const int hc = sub * 128 + i * 8 + j * 2;
            acc += f.x * ks[hc] + f.y * ks[hc + 1];
        }
        if (i < 8) d0 += acc; else d1 += acc;
    }
    const float inv0 = QN_SCALE / d0, inv1 = QN_SCALE / d1;

    uint4* qd = (uint4*)((char*)g_qn + rowofs);
#pragma unroll
    for (int i = 0; i < 16; i++) {
        const float inv = (i < 8) ? inv0 : inv1;
        uint32_t w[4] = {qv[i].x, qv[i].y, qv[i].z, qv[i].w};
#pragma unroll
        for (int j = 0; j < 4; j++) {
            float2 f = __half22float2(*reinterpret_cast<const __half2*>(&w[j]));
            __half2 o = __floats2half2_rn(f.x * inv, f.y * inv);
            w[j] = *reinterpret_cast<uint32_t*>(&o);
        }
        qd[i] = make_uint4(w[0], w[1], w[2], w[3]);
    }
}

// ---------------- final GEMM: 1-term (qn @ Ph^T)*QN_INV + bo, 3-stage ----------------
__global__ void __launch_bounds__(256, 2)
gemmF(const float* __restrict__ bo, float* __restrict__ Y)
{
    extern __shared__ char smem[];
    const uint32_t sb = smem_u32(smem);
    const int tid = threadIdx.x;
    const int wid = tid >> 5, lane = tid & 31;
    const int wm = wid >> 2, wn = wid & 3;
    const int g = lane >> 2, tg = lane & 3;
    const int m0 = blockIdx.y * 128, n0 = blockIdx.x * 128;
    const int b = blockIdx.y >> 6;
    const __half* Ph = g_Ph[b];

    float acc[4][4][4];
#pragma unroll
    for (int i = 0; i < 4; i++)
#pragma unroll
        for (int j = 0; j < 4; j++)
#pragma unroll
            for (int r = 0; r < 4; r++) acc[i][j][r] = 0.f;

    const int r0 = tid >> 3, u0 = tid & 7;
    const uint32_t dA = sb + G1_A + swz(r0, u0);
    const uint32_t dB = sb + G1_B + swz(r0, u0);
    const char* pA = (const char*)g_qn + ((size_t)(m0 + r0) * DDIM) * 2 + u0 * 16;
    const char* pB = (const char*)Ph   + ((size_t)(n0 + r0) * DDIM) * 2 + u0 * 16;

    auto issue = [&](int stage, int kc) {
        const uint32_t so = (uint32_t)(stage * G1_STAGE);
        const int ko = kc * 128;
#pragma unroll
        for (int it = 0; it < 4; it++) {
            cpasync16(dA + so + it * 4096, pA + it * 32768 + ko);
            cpasync16(dB + so + it * 4096, pB + it * 32768 + ko);
        }
        cp_commit();
    };

    uint32_t aB[4], bB[2];
#pragma unroll
    for (int mi = 0; mi < 4; mi++)
        aB[mi] = (uint32_t)G1_A + sbase(wm * 64 + mi * 16 + (lane & 15));
#pragma unroll
    for (int np = 0; np < 2; np++)
        bB[np] = (uint32_t)G1_B + sbase(wn * 32 + np * 16 + ((lane >> 4) << 3) + (lane & 7));
    const uint32_t aX = (uint32_t)(lane >> 4) << 4;
    const uint32_t bX = (uint32_t)((lane >> 3) & 1) << 4;

    issue(0, 0);
    issue(1, 1);

    for (int kc = 0; kc < NCH; kc++) {
        if (kc < NCH - 1) cp_wait1(); else cp_wait0();
        __syncthreads();
        if (kc + 2 < NCH) issue((kc + 2) % 3, kc + 2);

        const uint32_t st = sb + (kc % 3) * G1_STAGE;
#pragma unroll
        for (int ks = 0; ks < 4; ks++) {
            const uint32_t kx = (uint32_t)(ks * 2) << 4;
            uint32_t ah[4][4];
#pragma unroll
            for (int mi = 0; mi < 4; mi++)
                ldsm4(ah[mi], st + (aB[mi] ^ (kx | aX)));
#pragma unroll
            for (int np = 0; np < 2; np++) {
                uint32_t r4[4];
                ldsm4(r4, st + (bB[np] ^ (kx | bX)));
                uint32_t b0[2] = {r4[0], r4[1]}, b1[2] = {r4[2], r4[3]};
#pragma unroll
                for (int mi = 0; mi < 4; mi++) {
                    mma_f16(acc[mi][np*2+0], ah[mi], b0);
                    mma_f16(acc[mi][np*2+1], ah[mi], b1);
                }
            }
        }
        __syncthreads();
    }

#pragma unroll
    for (int mi = 0; mi < 4; mi++)
#pragma unroll
        for (int ni = 0; ni < 4; ni++) {
            const int col = n0 + wn * 32 + ni * 8 + tg * 2;
            const float b0 = bo[col], b1 = bo[col + 1];
#pragma unroll
            for (int half = 0; half < 2; half++) {
                const int row = m0 + wm * 64 + mi * 16 + g + half * 8;
                float2 o;
                o.x = acc[mi][ni][half * 2 + 0] * QN_INV + b0;
                o.y = acc[mi][ni][half * 2 + 1] * QN_INV + b1;
                *(float2*)(Y + (size_t)row * DDIM + col) = o;
            }
        }
}

// ---------------- launch ----------------
extern "C" void kernel_launch(void* const* d_in, const int* in_sizes, int n_in,
                              void* d_out, int out_size)
{
    const float* q  = (const float*)d_in[0];
    const float* k  = (const float*)d_in[1];
    const float* v  = (const float*)d_in[2];
    const float* Wq = (const float*)d_in[3];
    const float* bq = (const float*)d_in[4];
    const float* Wk = (const float*)d_in[5];
    const float* bk = (const float*)d_in[6];
    const float* Wv = (const float*)d_in[7];
    const float* bv = (const float*)d_in[8];
    const float* Wo = (const float*)d_in[9];
    const float* bo = (const float*)d_in[10];
    float* out = (float*)d_out;

    cudaFuncSetAttribute((const void*)gemm1, cudaFuncAttributeMaxDynamicSharedMemorySize, SM1);
    cudaFuncSetAttribute((const void*)gemmF, cudaFuncAttributeMaxDynamicSharedMemorySize, SM1);

    precvt_w1<<<dim3(256, 3), 256>>>(Wq, Wk, Wv);
    precvt_x<<<dim3(MM*DDIM/4/256, 3), 256>>>(q, k, v);
    zero_kernel<<<(BB*HH*DH*DH + 255)/256, 256>>>();
    gemm1<<<dim3(4, 256, 3), 256, SM1>>>(bq, bk, bv);            // qh/kh/vh fp16
    ctx_kernel<<<dim3(BB*HH, CTX_CHUNKS), 256>>>();              // ctx, ksum (HMMA)
    p_kernel<<<dim3(DDIM, BB), 256>>>(Wo);                       // PT fp16
    qn_kernel<<<dim3(TT/64, BB), 256>>>();                       // qn = qh*(S/den)
    gemmF<<<dim3(4, 256), 256, SM1>>>(bo, out);                  // out = qn@PT^T*1/S + bo
}